// round 12
// baseline (speedup 1.0000x reference)
#include <cuda_runtime.h>

// SPConv fused GNN, R9: edge kernel at TPB=1024 (32 warps/SM, 8ch x 2edge
// thread tiles) for 2x latency hiding; R8 algebra (Wm2 on node side) kept.

#define TPB 512        // pq/out kernels
#define TPB_E 1024     // edge kernel
#define TE 256         // edges (or nodes) per tile
#define AP 260         // activation smem pitch (floats, mult of 4)

typedef unsigned long long ull;

__device__ float g_cnt[65536];
__device__ int g_idx64;
__device__ float g_P[3276800];   // z @ Wm1[0:64]
__device__ float g_Q[3276800];   // z @ Wm1[64:128]

__device__ __forceinline__ void ffma2(ull& acc, ull a, ull b) {
    asm("fma.rn.f32x2 %0, %1, %2, %0;" : "+l"(acc) : "l"(a), "l"(b));
}
__device__ __forceinline__ ull dup2(float w) {
    ull r;
    asm("mov.b64 %0, {%1, %1};" : "=l"(r) : "r"(__float_as_uint(w)));
    return r;
}
__device__ __forceinline__ ull pack2(float lo, float hi) {
    ull r;
    asm("mov.b64 %0, {%1, %2};" : "=l"(r)
        : "r"(__float_as_uint(lo)), "r"(__float_as_uint(hi)));
    return r;
}
__device__ __forceinline__ void unpack2(ull v, float& lo, float& hi) {
    unsigned a, b;
    asm("mov.b64 {%0, %1}, %2;" : "=r"(a), "=r"(b) : "l"(v));
    lo = __uint_as_float(a);
    hi = __uint_as_float(b);
}
__device__ __forceinline__ void red_add_v4(float* p, float x, float y,
                                           float z, float w) {
    asm volatile("red.global.add.v4.f32 [%0], {%1, %2, %3, %4};"
                 :: "l"(p), "f"(x), "f"(y), "f"(z), "f"(w) : "memory");
}
// half-scoped barrier: 512 threads per edge-half
#define HALF_BAR(g) asm volatile("bar.sync %0, 512;" :: "r"((g) + 1) : "memory")

__global__ void detect_kernel(const unsigned long long* __restrict__ ei) {
    if (threadIdx.x == 0 && blockIdx.x == 0) {
        int is64 = 1;
        for (int i = 0; i < 64; ++i)
            if ((ei[i] >> 32) != 0ull) { is64 = 0; break; }
        g_idx64 = is64;
    }
}

__global__ void zero_kernel(float* __restrict__ sums, int total, int n) {
    int i = blockIdx.x * blockDim.x + threadIdx.x;
    if (i < total) sums[i] = 0.0f;
    if (i < n) g_cnt[i] = 0.0f;
}

// ======== 8ch x 2edge GEMM for edge kernel ========
// acc[4 ch-pairs][2 edges] += W[k][cb..cb+7] * H[k][eb..eb+1]
__device__ __forceinline__ void gemm2(const float* __restrict__ H, int hp,
                                      const float* __restrict__ W, int K,
                                      int cb, int eb, ull acc[4][2]) {
#pragma unroll 4
    for (int k = 0; k < K; ++k) {
        ulonglong2 wA = *reinterpret_cast<const ulonglong2*>(W + k * 64 + cb);
        ulonglong2 wB = *reinterpret_cast<const ulonglong2*>(W + k * 64 + cb + 4);
        ull w2[4] = {wA.x, wA.y, wB.x, wB.y};
        float2 h = *reinterpret_cast<const float2*>(H + k * hp + eb);
        ull h0 = dup2(h.x), h1 = dup2(h.y);
#pragma unroll
        for (int cp = 0; cp < 4; ++cp) {
            ffma2(acc[cp][0], w2[cp], h0);
            ffma2(acc[cp][1], w2[cp], h1);
        }
    }
}

__device__ __forceinline__ void zero2(ull acc[4][2]) {
#pragma unroll
    for (int cp = 0; cp < 4; ++cp) { acc[cp][0] = 0ull; acc[cp][1] = 0ull; }
}

// relu(acc + bias) -> D[ch][eb..eb+1] as float2 per ch row
__device__ __forceinline__ void store_relu2(float* __restrict__ D,
                                            ull acc[4][2],
                                            const float* __restrict__ bias,
                                            int cb, int eb) {
#pragma unroll
    for (int cp = 0; cp < 4; ++cp) {
        float l0, h0, l1, h1;
        unpack2(acc[cp][0], l0, h0);
        unpack2(acc[cp][1], l1, h1);
        float b0 = bias[cb + 2 * cp], b1 = bias[cb + 2 * cp + 1];
        float2 v0 = make_float2(fmaxf(l0 + b0, 0.0f), fmaxf(l1 + b0, 0.0f));
        float2 v1 = make_float2(fmaxf(h0 + b1, 0.0f), fmaxf(h1 + b1, 0.0f));
        *reinterpret_cast<float2*>(D + (cb + 2 * cp) * AP + eb) = v0;
        *reinterpret_cast<float2*>(D + (cb + 2 * cp + 1) * AP + eb) = v1;
    }
}

// ======== 8ch x 4edge GEMM (pq/out kernels, R8-proven) ========
__device__ __forceinline__ void gemmp(const float* __restrict__ H, int hp,
                                      const float* __restrict__ W, int K,
                                      int cb, int eb, ull acc[4][4]) {
#pragma unroll 4
    for (int k = 0; k < K; ++k) {
        ulonglong2 wA = *reinterpret_cast<const ulonglong2*>(W + k * 64 + cb);
        ulonglong2 wB = *reinterpret_cast<const ulonglong2*>(W + k * 64 + cb + 4);
        ull w2[4] = {wA.x, wA.y, wB.x, wB.y};
        float4 h = *reinterpret_cast<const float4*>(H + k * hp + eb);
        ull h2[4] = {dup2(h.x), dup2(h.y), dup2(h.z), dup2(h.w)};
#pragma unroll
        for (int cp = 0; cp < 4; ++cp)
#pragma unroll
            for (int e = 0; e < 4; ++e)
                ffma2(acc[cp][e], w2[cp], h2[e]);
    }
}

__device__ __forceinline__ void zero_acc(ull acc[4][4]) {
#pragma unroll
    for (int cp = 0; cp < 4; ++cp)
#pragma unroll
        for (int e = 0; e < 4; ++e) acc[cp][e] = 0ull;
}

// ---- pq_kernel: P = z @ Wm1[0:64], Q = z @ Wm1[64:128] ----
// smem: sW 8192 | sZ 64*AP=16640  -> 24832 floats
__global__ __launch_bounds__(TPB) void pq_kernel(
    const float* __restrict__ z, const float* __restrict__ Wm1,
    int N, int ntiles) {
    extern __shared__ float sm[];
    float* sW = sm;
    float* sZ = sm + 8192;
    const int tid = threadIdx.x;
    for (int i = tid; i < 8192; i += TPB) sW[i] = Wm1[i];
    __syncthreads();

    const int wid = tid >> 5, lane = tid & 31;
    const int grp = wid >> 3;
    const int cb = (wid & 7) * 8;
    const int eb = grp * 128 + lane * 4;

    for (int tile = blockIdx.x; tile < ntiles; tile += gridDim.x) {
        const int base = tile * TE;
        for (int i = tid; i < 64 * TE; i += TPB) {
            int nl = i >> 6, k = i & 63;
            int gn = base + nl;
            sZ[k * AP + nl] = (gn < N) ? z[(size_t)gn * 64 + k] : 0.0f;
        }
        __syncthreads();

        ull acc[4][4];
#pragma unroll
        for (int pass = 0; pass < 2; ++pass) {
            zero_acc(acc);
            gemmp(sZ, AP, sW + pass * 64 * 64, 64, cb, eb, acc);
            float* dst = pass == 0 ? g_P : g_Q;
#pragma unroll
            for (int e = 0; e < 4; ++e) {
                int gn = base + eb + e;
                if (gn < N) {
                    float v[8];
#pragma unroll
                    for (int cp = 0; cp < 4; ++cp)
                        unpack2(acc[cp][e], v[2 * cp], v[2 * cp + 1]);
                    *reinterpret_cast<float4*>(&dst[(size_t)gn * 64 + cb]) =
                        make_float4(v[0], v[1], v[2], v[3]);
                    *reinterpret_cast<float4*>(&dst[(size_t)gn * 64 + cb + 4]) =
                        make_float4(v[4], v[5], v[6], v[7]);
                }
            }
        }
        __syncthreads();
    }
}

// ======== edge_kernel (TPB_E = 1024) ========
// smem floats:
//      0 : sWe2  4096
//   4096 : sWm1c 4096  (Wm1 rows 128..191)
//   8192 : sWe1   192
//   8384 : be1 64 | 8448 : be2 64 | 8512 : bm1 64
//   8576 : sDelta 3*AP = 780
//   9356 : sA 64*AP = 16640
//  25996 : sB 16640
//  42636 : src/dst (2*TE ints)
__global__ __launch_bounds__(TPB_E) void edge_kernel(
    const float* __restrict__ cent, const void* __restrict__ ei_raw,
    const float* __restrict__ We1, const float* __restrict__ be1,
    const float* __restrict__ We2, const float* __restrict__ be2,
    const float* __restrict__ Wm1, const float* __restrict__ bm1,
    float* __restrict__ S1, int E, int N, int ntiles) {
    extern __shared__ float sm[];
    float* sWe2 = sm;
    float* sWm1c = sm + 4096;
    float* sWe1 = sm + 8192;
    float* sbe1 = sm + 8384;
    float* sbe2 = sm + 8448;
    float* sbm1 = sm + 8512;
    float* sDelta = sm + 8576;
    float* sA = sm + 9356;
    float* sB = sm + 25996;
    int* sSrc = (int*)(sm + 42636);
    int* sDst = sSrc + TE;

    const int tid = threadIdx.x;
    const int idx64 = g_idx64;
    const long long* ei64 = (const long long*)ei_raw;
    const int* ei32 = (const int*)ei_raw;

    for (int i = tid; i < 4096; i += TPB_E) {
        sWe2[i] = We2[i];
        sWm1c[i] = Wm1[128 * 64 + i];
    }
    if (tid < 192) sWe1[tid] = We1[tid];
    if (tid >= 256 && tid < 320) {
        int t = tid - 256;
        sbe1[t] = be1[t]; sbe2[t] = be2[t]; sbm1[t] = bm1[t];
    }
    __syncthreads();

    const int wid = tid >> 5, lane = tid & 31;
    const int chgrp = wid & 7;                // 8 channel groups
    const int egrp = wid >> 3;                // 4 edge groups of 64 edges
    const int half = egrp >> 1;               // 0: edges 0-127, 1: 128-255
    const int cb = chgrp * 8;                 // 8 channels
    const int eb = egrp * 64 + lane * 2;      // 2 edges

    for (int tile = blockIdx.x; tile < ntiles; tile += gridDim.x) {
        const int base = tile * TE;

        if (tid < TE) {
            int e = base + tid;
            int s = 0, d = -1;
            if (e < E) {
                if (idx64) { s = (int)ei64[e]; d = (int)ei64[(size_t)E + e]; }
                else       { s = ei32[e];      d = ei32[E + e]; }
                if (s < 0 || s >= N) s = 0;
                if (d < 0 || d >= N) d = 0;
            }
            sSrc[tid] = s;
            sDst[tid] = d;
        }
        __syncthreads();

        // delta = centroids[dst] - centroids[src]
        if (tid < 3 * TE) {
            int e = tid & (TE - 1), comp = tid >> 8;
            int s = sSrc[e], d = sDst[e];
            int dd = (d < 0) ? s : d;
            sDelta[comp * AP + e] =
                cent[(size_t)dd * 3 + comp] - cent[(size_t)s * 3 + comp];
        }
        __syncthreads();

        ull acc[4][2];   // layer scratch
        ull accm[4][2];  // m1 accumulator (init PQ, finished by L3)

        // L1: e1 = relu(delta @ We1 + be1) -> sA
        zero2(acc);
        gemm2(sDelta, AP, sWe1, 3, cb, eb, acc);
        store_relu2(sA, acc, sbe1, cb, eb);
        HALF_BAR(half);

        // PQ init for m1 (global loads; latency overlapped with L2 gemm)
#pragma unroll
        for (int e = 0; e < 2; ++e) {
            int ed = eb + e;
            int s = sSrc[ed], d = sDst[ed];
            int dd = (d < 0) ? s : d;
            float4 p0 = *reinterpret_cast<const float4*>(&g_P[(size_t)s * 64 + cb]);
            float4 p1 = *reinterpret_cast<const float4*>(&g_P[(size_t)s * 64 + cb + 4]);
            float4 q0 = *reinterpret_cast<const float4*>(&g_Q[(size_t)dd * 64 + cb]);
            float4 q1 = *reinterpret_cast<const float4*>(&g_Q[(size_t)dd * 64 + cb + 4]);
            accm[0][e] = pack2(p0.x + q0.x, p0.y + q0.y);
            accm[1][e] = pack2(p0.z + q0.z, p0.w + q0.w);
            accm[2][e] = pack2(p1.x + q1.x, p1.y + q1.y);
            accm[3][e] = pack2(p1.z + q1.z, p1.w + q1.w);
        }

        // L2: e = relu(e1 @ We2 + be2) -> sB
        zero2(acc);
        gemm2(sA, AP, sWe2, 64, cb, eb, acc);
        store_relu2(sB, acc, sbe2, cb, eb);
        HALF_BAR(half);

        // L3: m1 = relu(e @ Wm1c + PQ + bm1) -> vec4 scatter-add into S1[dst]
        gemm2(sB, AP, sWm1c, 64, cb, eb, accm);
#pragma unroll
        for (int e = 0; e < 2; ++e) {
            int d = sDst[eb + e];
            if (d >= 0) {
                float v[8];
#pragma unroll
                for (int cp = 0; cp < 4; ++cp)
                    unpack2(accm[cp][e], v[2 * cp], v[2 * cp + 1]);
#pragma unroll
                for (int i = 0; i < 8; ++i)
                    v[i] = fmaxf(v[i] + sbm1[cb + i], 0.0f);
                float* p = &S1[(size_t)d * 64 + cb];
                red_add_v4(p, v[0], v[1], v[2], v[3]);
                red_add_v4(p + 4, v[4], v[5], v[6], v[7]);
            }
        }
        if (tid < TE && sDst[tid] >= 0) atomicAdd(&g_cnt[sDst[tid]], 1.0f);
        __syncthreads();
    }
}

// ---- out_kernel ----
// M = (S1 @ Wm2 + cnt*bm2) / max(cnt,1);  out = relu([z, M] @ Wu1 + bu1)
// smem floats: 0: sWu1 8192 | 8192: sWm2 4096 | 12288: bu1 64 | 12352: bm2 64
//              12416: sZM 128*AP = 33280   -> 45696 floats
__global__ __launch_bounds__(TPB) void out_kernel(
    const float* __restrict__ z, const float* __restrict__ S1,
    const float* __restrict__ Wu1, const float* __restrict__ bu1,
    const float* __restrict__ Wm2, const float* __restrict__ bm2,
    float* __restrict__ out, int N, int ntiles) {
    extern __shared__ float sm[];
    float* sWu1 = sm;
    float* sWm2 = sm + 8192;
    float* sbu1 = sm + 12288;
    float* sbm2 = sm + 12352;
    float* sZM = sm + 12416;

    const int tid = threadIdx.x;
    for (int i = tid; i < 8192; i += TPB) sWu1[i] = Wu1[i];
    for (int i = tid; i < 4096; i += TPB) sWm2[i] = Wm2[i];
    if (tid < 64) { sbu1[tid] = bu1[tid]; sbm2[tid] = bm2[tid]; }
    __syncthreads();

    const int wid = tid >> 5, lane = tid & 31;
    const int grp = wid >> 3;
    const int cb = (wid & 7) * 8;
    const int eb = grp * 128 + lane * 4;

    for (int tile = blockIdx.x; tile < ntiles; tile += gridDim.x) {
        const int base = tile * TE;
        for (int i = tid; i < 64 * TE; i += TPB) {
            int nl = i >> 6, k = i & 63;
            int gn = base + nl;
            float zv = 0.0f, sv = 0.0f;
            if (gn < N) {
                zv = z[(size_t)gn * 64 + k];
                sv = S1[(size_t)gn * 64 + k];
            }
            sZM[k * AP + nl] = zv;
            sZM[(64 + k) * AP + nl] = sv;
        }
        __syncthreads();

        // stage 1: Mpre = S1tile @ Wm2
        ull acc[4][4];
        zero_acc(acc);
        gemmp(sZM + 64 * AP, AP, sWm2, 64, cb, eb, acc);

        float Mv[4][8];
#pragma unroll
        for (int e = 0; e < 4; ++e) {
            int gn = base + eb + e;
            float c = (gn < N) ? g_cnt[gn] : 0.0f;
            float rinv = 1.0f / fmaxf(c, 1.0f);
#pragma unroll
            for (int cp = 0; cp < 4; ++cp) {
                float lo, hi;
                unpack2(acc[cp][e], lo, hi);
                Mv[e][2 * cp] = (lo + c * sbm2[cb + 2 * cp]) * rinv;
                Mv[e][2 * cp + 1] = (hi + c * sbm2[cb + 2 * cp + 1]) * rinv;
            }
        }
        __syncthreads();

#pragma unroll
        for (int cp = 0; cp < 4; ++cp) {
            float4 v0 = make_float4(Mv[0][2 * cp], Mv[1][2 * cp],
                                    Mv[2][2 * cp], Mv[3][2 * cp]);
            float4 v1 = make_float4(Mv[0][2 * cp + 1], Mv[1][2 * cp + 1],
                                    Mv[2][2 * cp + 1], Mv[3][2 * cp + 1]);
            *reinterpret_cast<float4*>(sZM + (64 + cb + 2 * cp) * AP + eb) = v0;
            *reinterpret_cast<float4*>(sZM + (64 + cb + 2 * cp + 1) * AP + eb) = v1;
        }
        __syncthreads();

        // stage 2: out = relu([z, M] @ Wu1 + bu1)
        zero_acc(acc);
        gemmp(sZM, AP, sWu1, 128, cb, eb, acc);
#pragma unroll
        for (int e = 0; e < 4; ++e) {
            int gn = base + eb + e;
            if (gn < N) {
                float v[8];
#pragma unroll
                for (int cp = 0; cp < 4; ++cp)
                    unpack2(acc[cp][e], v[2 * cp], v[2 * cp + 1]);
                float4 o0, o1;
                o0.x = fmaxf(v[0] + sbu1[cb + 0], 0.0f);
                o0.y = fmaxf(v[1] + sbu1[cb + 1], 0.0f);
                o0.z = fmaxf(v[2] + sbu1[cb + 2], 0.0f);
                o0.w = fmaxf(v[3] + sbu1[cb + 3], 0.0f);
                o1.x = fmaxf(v[4] + sbu1[cb + 4], 0.0f);
                o1.y = fmaxf(v[5] + sbu1[cb + 5], 0.0f);
                o1.z = fmaxf(v[6] + sbu1[cb + 6], 0.0f);
                o1.w = fmaxf(v[7] + sbu1[cb + 7], 0.0f);
                *reinterpret_cast<float4*>(&out[(size_t)gn * 64 + cb]) = o0;
                *reinterpret_cast<float4*>(&out[(size_t)gn * 64 + cb + 4]) = o1;
            }
        }
        __syncthreads();
    }
}

extern "C" void kernel_launch(void* const* d_in, const int* in_sizes, int n_in,
                              void* d_out, int out_size) {
    const float* z    = (const float*)d_in[0];
    const float* cent = (const float*)d_in[1];
    const void* ei    = d_in[2];
    const float* We1 = (const float*)d_in[3];
    const float* be1 = (const float*)d_in[4];
    const float* We2 = (const float*)d_in[5];
    const float* be2 = (const float*)d_in[6];
    const float* Wm1 = (const float*)d_in[7];
    const float* bm1 = (const float*)d_in[8];
    const float* Wm2 = (const float*)d_in[9];
    const float* bm2 = (const float*)d_in[10];
    const float* Wu1 = (const float*)d_in[11];
    const float* bu1 = (const float*)d_in[12];
    float* out = (float*)d_out;

    const int N = in_sizes[0] / 64;
    const int E = in_sizes[2] / 2;
    const int ntiles_e = (E + TE - 1) / TE;
    const int ntiles_n = (N + TE - 1) / TE;

    const size_t smem_edge = 42636 * sizeof(float) + 2 * TE * sizeof(int);
    const size_t smem_pq   = 24832 * sizeof(float);
    const size_t smem_out  = 45696 * sizeof(float);

    cudaFuncSetAttribute(edge_kernel, cudaFuncAttributeMaxDynamicSharedMemorySize,
                         (int)smem_edge);
    cudaFuncSetAttribute(pq_kernel, cudaFuncAttributeMaxDynamicSharedMemorySize,
                         (int)smem_pq);
    cudaFuncSetAttribute(out_kernel, cudaFuncAttributeMaxDynamicSharedMemorySize,
                         (int)smem_out);

    detect_kernel<<<1, 32>>>((const unsigned long long*)ei);
    zero_kernel<<<(N * 64 + 255) / 256, 256>>>(out, N * 64, N);
    pq_kernel<<<ntiles_n, TPB, smem_pq>>>(z, Wm1, N, ntiles_n);
    edge_kernel<<<148, TPB_E, smem_edge>>>(cent, ei,
                                           We1, be1, We2, be2,
                                           Wm1, bm1,
                                           out, E, N, ntiles_e);
    out_kernel<<<ntiles_n, TPB, smem_out>>>(z, out, Wu1, bu1, Wm2, bm2,
                                            out, N, ntiles_n);
}

// round 14
// speedup vs baseline: 1.0207x; 1.0207x over previous
#include <cuda_runtime.h>

// SPConv fused GNN, R14: R13 (single activation buffer, 2 CTAs/SM) with the
// delta-staging loop bug fixed (for-loop covers all 3*TE items at TPB=512).

#define TPB 512
#define TE 256        // edges (or nodes) per tile
#define AP 260        // activation smem pitch (floats, mult of 4)

typedef unsigned long long ull;

__device__ float g_cnt[65536];
__device__ int g_idx64;
__device__ float g_P[3276800];   // z @ Wm1[0:64]
__device__ float g_Q[3276800];   // z @ Wm1[64:128]

__device__ __forceinline__ void ffma2(ull& acc, ull a, ull b) {
    asm("fma.rn.f32x2 %0, %1, %2, %0;" : "+l"(acc) : "l"(a), "l"(b));
}
__device__ __forceinline__ ull dup2(float w) {
    ull r;
    asm("mov.b64 %0, {%1, %1};" : "=l"(r) : "r"(__float_as_uint(w)));
    return r;
}
__device__ __forceinline__ ull pack2(float lo, float hi) {
    ull r;
    asm("mov.b64 %0, {%1, %2};" : "=l"(r)
        : "r"(__float_as_uint(lo)), "r"(__float_as_uint(hi)));
    return r;
}
__device__ __forceinline__ void unpack2(ull v, float& lo, float& hi) {
    unsigned a, b;
    asm("mov.b64 {%0, %1}, %2;" : "=r"(a), "=r"(b) : "l"(v));
    lo = __uint_as_float(a);
    hi = __uint_as_float(b);
}
__device__ __forceinline__ void red_add_v4(float* p, float x, float y,
                                           float z, float w) {
    asm volatile("red.global.add.v4.f32 [%0], {%1, %2, %3, %4};"
                 :: "l"(p), "f"(x), "f"(y), "f"(z), "f"(w) : "memory");
}
// half-scoped barrier: 256 threads (8 warps) per edge-half
#define HALF_BAR(g) asm volatile("bar.sync %0, 256;" :: "r"((g) + 1) : "memory")

__global__ void detect_kernel(const unsigned long long* __restrict__ ei) {
    if (threadIdx.x == 0 && blockIdx.x == 0) {
        int is64 = 1;
        for (int i = 0; i < 64; ++i)
            if ((ei[i] >> 32) != 0ull) { is64 = 0; break; }
        g_idx64 = is64;
    }
}

__global__ void zero_kernel(float* __restrict__ sums, int total, int n) {
    int i = blockIdx.x * blockDim.x + threadIdx.x;
    if (i < total) sums[i] = 0.0f;
    if (i < n) g_cnt[i] = 0.0f;
}

// acc[4 ch-pairs][4 edges] += W[k][cb..cb+7] * H[k][eb..eb+3]
__device__ __forceinline__ void gemmp(const float* __restrict__ H, int hp,
                                      const float* __restrict__ W, int K,
                                      int cb, int eb, ull acc[4][4]) {
#pragma unroll 4
    for (int k = 0; k < K; ++k) {
        ulonglong2 wA = *reinterpret_cast<const ulonglong2*>(W + k * 64 + cb);
        ulonglong2 wB = *reinterpret_cast<const ulonglong2*>(W + k * 64 + cb + 4);
        ull w2[4] = {wA.x, wA.y, wB.x, wB.y};
        float4 h = *reinterpret_cast<const float4*>(H + k * hp + eb);
        ull h2[4] = {dup2(h.x), dup2(h.y), dup2(h.z), dup2(h.w)};
#pragma unroll
        for (int cp = 0; cp < 4; ++cp)
#pragma unroll
            for (int e = 0; e < 4; ++e)
                ffma2(acc[cp][e], w2[cp], h2[e]);
    }
}

__device__ __forceinline__ void zero_acc(ull acc[4][4]) {
#pragma unroll
    for (int cp = 0; cp < 4; ++cp)
#pragma unroll
        for (int e = 0; e < 4; ++e) acc[cp][e] = 0ull;
}

// relu(acc + bias) -> D[ch][eb..eb+3] dense float4 rows
__device__ __forceinline__ void store_relu(float* __restrict__ D,
                                           ull acc[4][4],
                                           const float* __restrict__ bias,
                                           int cb, int eb) {
#pragma unroll
    for (int cp = 0; cp < 4; ++cp) {
        float lo[4], hi[4];
#pragma unroll
        for (int e = 0; e < 4; ++e) unpack2(acc[cp][e], lo[e], hi[e]);
        float b0 = bias[cb + 2 * cp], b1 = bias[cb + 2 * cp + 1];
        float4 v0, v1;
        v0.x = fmaxf(lo[0] + b0, 0.0f); v0.y = fmaxf(lo[1] + b0, 0.0f);
        v0.z = fmaxf(lo[2] + b0, 0.0f); v0.w = fmaxf(lo[3] + b0, 0.0f);
        v1.x = fmaxf(hi[0] + b1, 0.0f); v1.y = fmaxf(hi[1] + b1, 0.0f);
        v1.z = fmaxf(hi[2] + b1, 0.0f); v1.w = fmaxf(hi[3] + b1, 0.0f);
        *reinterpret_cast<float4*>(D + (cb + 2 * cp) * AP + eb) = v0;
        *reinterpret_cast<float4*>(D + (cb + 2 * cp + 1) * AP + eb) = v1;
    }
}

// ---- pq_kernel: P = z @ Wm1[0:64], Q = z @ Wm1[64:128] ----
// smem: sW 8192 | sZ 64*AP=16640  -> 24832 floats
__global__ __launch_bounds__(TPB) void pq_kernel(
    const float* __restrict__ z, const float* __restrict__ Wm1,
    int N, int ntiles) {
    extern __shared__ float sm[];
    float* sW = sm;
    float* sZ = sm + 8192;
    const int tid = threadIdx.x;
    for (int i = tid; i < 8192; i += TPB) sW[i] = Wm1[i];
    __syncthreads();

    const int wid = tid >> 5, lane = tid & 31;
    const int grp = wid >> 3;
    const int cb = (wid & 7) * 8;
    const int eb = grp * 128 + lane * 4;

    for (int tile = blockIdx.x; tile < ntiles; tile += gridDim.x) {
        const int base = tile * TE;
        for (int i = tid; i < 64 * TE; i += TPB) {
            int nl = i >> 6, k = i & 63;
            int gn = base + nl;
            sZ[k * AP + nl] = (gn < N) ? z[(size_t)gn * 64 + k] : 0.0f;
        }
        __syncthreads();

        ull acc[4][4];
#pragma unroll
        for (int pass = 0; pass < 2; ++pass) {
            zero_acc(acc);
            gemmp(sZ, AP, sW + pass * 64 * 64, 64, cb, eb, acc);
            float* dst = pass == 0 ? g_P : g_Q;
#pragma unroll
            for (int e = 0; e < 4; ++e) {
                int gn = base + eb + e;
                if (gn < N) {
                    float v[8];
#pragma unroll
                    for (int cp = 0; cp < 4; ++cp)
                        unpack2(acc[cp][e], v[2 * cp], v[2 * cp + 1]);
                    *reinterpret_cast<float4*>(&dst[(size_t)gn * 64 + cb]) =
                        make_float4(v[0], v[1], v[2], v[3]);
                    *reinterpret_cast<float4*>(&dst[(size_t)gn * 64 + cb + 4]) =
                        make_float4(v[4], v[5], v[6], v[7]);
                }
            }
        }
        __syncthreads();
    }
}

// ======== edge_kernel (2 CTAs/SM) ========
// smem floats:
//      0 : sWe2  4096
//   4096 : sWm1c 4096  (Wm1 rows 128..191)
//   8192 : sWe1   192
//   8384 : be1 64 | 8448 : be2 64 | 8512 : bm1 64
//   8576 : sDelta 3*AP = 780
//   9356 : sBuf 64*AP = 16640    (e1, then e, reused)
//  25996 : src/dst (2*TE ints = 512 floats)
// total 26508 floats = 106,032 B -> 2 CTAs/SM
__global__ __launch_bounds__(TPB, 2) void edge_kernel(
    const float* __restrict__ cent, const void* __restrict__ ei_raw,
    const float* __restrict__ We1, const float* __restrict__ be1,
    const float* __restrict__ We2, const float* __restrict__ be2,
    const float* __restrict__ Wm1, const float* __restrict__ bm1,
    float* __restrict__ S1, int E, int N, int ntiles) {
    extern __shared__ float sm[];
    float* sWe2 = sm;
    float* sWm1c = sm + 4096;
    float* sWe1 = sm + 8192;
    float* sbe1 = sm + 8384;
    float* sbe2 = sm + 8448;
    float* sbm1 = sm + 8512;
    float* sDelta = sm + 8576;
    float* sBuf = sm + 9356;
    int* sSrc = (int*)(sm + 25996);
    int* sDst = sSrc + TE;

    const int tid = threadIdx.x;
    const int idx64 = g_idx64;
    const long long* ei64 = (const long long*)ei_raw;
    const int* ei32 = (const int*)ei_raw;

    for (int i = tid; i < 4096; i += TPB) {
        sWe2[i] = We2[i];
        sWm1c[i] = Wm1[128 * 64 + i];
    }
    if (tid < 192) sWe1[tid] = We1[tid];
    if (tid >= 256 && tid < 320) {
        int t = tid - 256;
        sbe1[t] = be1[t]; sbe2[t] = be2[t]; sbm1[t] = bm1[t];
    }
    __syncthreads();

    const int wid = tid >> 5, lane = tid & 31;
    const int grp = wid >> 3;                 // 0: edges 0-127, 1: 128-255
    const int cb = (wid & 7) * 8;             // 8 channels
    const int eb = grp * 128 + lane * 4;      // 4 edges

    for (int tile = blockIdx.x; tile < ntiles; tile += gridDim.x) {
        const int base = tile * TE;

        if (tid < TE) {
            int e = base + tid;
            int s = 0, d = -1;
            if (e < E) {
                if (idx64) { s = (int)ei64[e]; d = (int)ei64[(size_t)E + e]; }
                else       { s = ei32[e];      d = ei32[E + e]; }
                if (s < 0 || s >= N) s = 0;
                if (d < 0 || d >= N) d = 0;
            }
            sSrc[tid] = s;
            sDst[tid] = d;
        }
        __syncthreads();

        // delta = centroids[dst] - centroids[src]  (FIX: full 3*TE coverage)
        for (int i = tid; i < 3 * TE; i += TPB) {
            int e = i & (TE - 1), comp = i >> 8;
            int s = sSrc[e], d = sDst[e];
            int dd = (d < 0) ? s : d;
            sDelta[comp * AP + e] =
                cent[(size_t)dd * 3 + comp] - cent[(size_t)s * 3 + comp];
        }
        __syncthreads();

        ull acc[4][4];

        // L1: e1 = relu(delta @ We1 + be1) -> sBuf
        zero_acc(acc);
        gemmp(sDelta, AP, sWe1, 3, cb, eb, acc);
        store_relu(sBuf, acc, sbe1, cb, eb);
        HALF_BAR(grp);

        // L2: e = relu(e1 @ We2 + be2); reuse sBuf (read -> bar -> write)
        zero_acc(acc);
        gemmp(sBuf, AP, sWe2, 64, cb, eb, acc);
        HALF_BAR(grp);                       // all reads of e1 complete
        store_relu(sBuf, acc, sbe2, cb, eb);
        HALF_BAR(grp);

        // L3: m1 = relu(e @ Wm1c + P[src] + Q[dst] + bm1) -> scatter S1[dst]
        {
            ull accm[4][4];
#pragma unroll
            for (int e = 0; e < 4; ++e) {
                int ed = eb + e;
                int s = sSrc[ed], d = sDst[ed];
                int dd = (d < 0) ? s : d;
                float4 p0 = *reinterpret_cast<const float4*>(&g_P[(size_t)s * 64 + cb]);
                float4 p1 = *reinterpret_cast<const float4*>(&g_P[(size_t)s * 64 + cb + 4]);
                float4 q0 = *reinterpret_cast<const float4*>(&g_Q[(size_t)dd * 64 + cb]);
                float4 q1 = *reinterpret_cast<const float4*>(&g_Q[(size_t)dd * 64 + cb + 4]);
                accm[0][e] = pack2(p0.x + q0.x, p0.y + q0.y);
                accm[1][e] = pack2(p0.z + q0.z, p0.w + q0.w);
                accm[2][e] = pack2(p1.x + q1.x, p1.y + q1.y);
                accm[3][e] = pack2(p1.z + q1.z, p1.w + q1.w);
            }
            gemmp(sBuf, AP, sWm1c, 64, cb, eb, accm);
#pragma unroll
            for (int e = 0; e < 4; ++e) {
                int d = sDst[eb + e];
                if (d >= 0) {
                    float v[8];
#pragma unroll
                    for (int cp = 0; cp < 4; ++cp)
                        unpack2(accm[cp][e], v[2 * cp], v[2 * cp + 1]);
#pragma unroll
                    for (int i = 0; i < 8; ++i)
                        v[i] = fmaxf(v[i] + sbm1[cb + i], 0.0f);
                    float* p = &S1[(size_t)d * 64 + cb];
                    red_add_v4(p, v[0], v[1], v[2], v[3]);
                    red_add_v4(p + 4, v[4], v[5], v[6], v[7]);
                }
            }
        }
        if (tid < TE && sDst[tid] >= 0) atomicAdd(&g_cnt[sDst[tid]], 1.0f);
        __syncthreads();
    }
}

// ---- out_kernel ----
// M = (S1 @ Wm2 + cnt*bm2) / max(cnt,1);  out = relu([z, M] @ Wu1 + bu1)
// smem floats: 0: sWu1 8192 | 8192: sWm2 4096 | 12288: bu1 64 | 12352: bm2 64
//              12416: sZM 128*AP = 33280   -> 45696 floats
__global__ __launch_bounds__(TPB) void out_kernel(
    const float* __restrict__ z, const float* __restrict__ S1,
    const float* __restrict__ Wu1, const float* __restrict__ bu1,
    const float* __restrict__ Wm2, const float* __restrict__ bm2,
    float* __restrict__ out, int N, int ntiles) {
    extern __shared__ float sm[];
    float* sWu1 = sm;
    float* sWm2 = sm + 8192;
    float* sbu1 = sm + 12288;
    float* sbm2 = sm + 12352;
    float* sZM = sm + 12416;

    const int tid = threadIdx.x;
    for (int i = tid; i < 8192; i += TPB) sWu1[i] = Wu1[i];
    for (int i = tid; i < 4096; i += TPB) sWm2[i] = Wm2[i];
    if (tid < 64) { sbu1[tid] = bu1[tid]; sbm2[tid] = bm2[tid]; }
    __syncthreads();

    const int wid = tid >> 5, lane = tid & 31;
    const int grp = wid >> 3;
    const int cb = (wid & 7) * 8;
    const int eb = grp * 128 + lane * 4;

    for (int tile = blockIdx.x; tile < ntiles; tile += gridDim.x) {
        const int base = tile * TE;
        for (int i = tid; i < 64 * TE; i += TPB) {
            int nl = i >> 6, k = i & 63;
            int gn = base + nl;
            float zv = 0.0f, sv = 0.0f;
            if (gn < N) {
                zv = z[(size_t)gn * 64 + k];
                sv = S1[(size_t)gn * 64 + k];
            }
            sZM[k * AP + nl] = zv;
            sZM[(64 + k) * AP + nl] = sv;
        }
        __syncthreads();

        // stage 1: Mpre = S1tile @ Wm2
        ull acc[4][4];
        zero_acc(acc);
        gemmp(sZM + 64 * AP, AP, sWm2, 64, cb, eb, acc);

        float Mv[4][8];
#pragma unroll
        for (int e = 0; e < 4; ++e) {
            int gn = base + eb + e;
            float c = (gn < N) ? g_cnt[gn] : 0.0f;
            float rinv = 1.0f / fmaxf(c, 1.0f);
#pragma unroll
            for (int cp = 0; cp < 4; ++cp) {
                float lo, hi;
                unpack2(acc[cp][e], lo, hi);
                Mv[e][2 * cp] = (lo + c * sbm2[cb + 2 * cp]) * rinv;
                Mv[e][2 * cp + 1] = (hi + c * sbm2[cb + 2 * cp + 1]) * rinv;
            }
        }
        __syncthreads();

#pragma unroll
        for (int cp = 0; cp < 4; ++cp) {
            float4 v0 = make_float4(Mv[0][2 * cp], Mv[1][2 * cp],
                                    Mv[2][2 * cp], Mv[3][2 * cp]);
            float4 v1 = make_float4(Mv[0][2 * cp + 1], Mv[1][2 * cp + 1],
                                    Mv[2][2 * cp + 1], Mv[3][2 * cp + 1]);
            *reinterpret_cast<float4*>(sZM + (64 + cb + 2 * cp) * AP + eb) = v0;
            *reinterpret_cast<float4*>(sZM + (64 + cb + 2 * cp + 1) * AP + eb) = v1;
        }
        __syncthreads();

        // stage 2: out = relu([z, M] @ Wu1 + bu1)
        zero_acc(acc);
        gemmp(sZM, AP, sWu1, 128, cb, eb, acc);
#pragma unroll
        for (int e = 0; e < 4; ++e) {
            int gn = base + eb + e;
            if (gn < N) {
                float v[8];
#pragma unroll
                for (int cp = 0; cp < 4; ++cp)
                    unpack2(acc[cp][e], v[2 * cp], v[2 * cp + 1]);
                float4 o0, o1;
                o0.x = fmaxf(v[0] + sbu1[cb + 0], 0.0f);
                o0.y = fmaxf(v[1] + sbu1[cb + 1], 0.0f);
                o0.z = fmaxf(v[2] + sbu1[cb + 2], 0.0f);
                o0.w = fmaxf(v[3] + sbu1[cb + 3], 0.0f);
                o1.x = fmaxf(v[4] + sbu1[cb + 4], 0.0f);
                o1.y = fmaxf(v[5] + sbu1[cb + 5], 0.0f);
                o1.z = fmaxf(v[6] + sbu1[cb + 6], 0.0f);
                o1.w = fmaxf(v[7] + sbu1[cb + 7], 0.0f);
                *reinterpret_cast<float4*>(&out[(size_t)gn * 64 + cb]) = o0;
                *reinterpret_cast<float4*>(&out[(size_t)gn * 64 + cb + 4]) = o1;
            }
        }
        __syncthreads();
    }
}

extern "C" void kernel_launch(void* const* d_in, const int* in_sizes, int n_in,
                              void* d_out, int out_size) {
    const float* z    = (const float*)d_in[0];
    const float* cent = (const float*)d_in[1];
    const void* ei    = d_in[2];
    const float* We1 = (const float*)d_in[3];
    const float* be1 = (const float*)d_in[4];
    const float* We2 = (const float*)d_in[5];
    const float* be2 = (const float*)d_in[6];
    const float* Wm1 = (const float*)d_in[7];
    const float* bm1 = (const float*)d_in[8];
    const float* Wm2 = (const float*)d_in[9];
    const float* bm2 = (const float*)d_in[10];
    const float* Wu1 = (const float*)d_in[11];
    const float* bu1 = (const float*)d_in[12];
    float* out = (float*)d_out;

    const int N = in_sizes[0] / 64;
    const int E = in_sizes[2] / 2;
    const int ntiles_e = (E + TE - 1) / TE;
    const int ntiles_n = (N + TE - 1) / TE;

    const size_t smem_edge = 25996 * sizeof(float) + 2 * TE * sizeof(int);
    const size_t smem_pq   = 24832 * sizeof(float);
    const size_t smem_out  = 45696 * sizeof(float);

    cudaFuncSetAttribute(edge_kernel, cudaFuncAttributeMaxDynamicSharedMemorySize,
                         (int)smem_edge);
    cudaFuncSetAttribute(pq_kernel, cudaFuncAttributeMaxDynamicSharedMemorySize,
                         (int)smem_pq);
    cudaFuncSetAttribute(out_kernel, cudaFuncAttributeMaxDynamicSharedMemorySize,
                         (int)smem_out);

    detect_kernel<<<1, 32>>>((const unsigned long long*)ei);
    zero_kernel<<<(N * 64 + 255) / 256, 256>>>(out, N * 64, N);
    pq_kernel<<<ntiles_n, TPB, smem_pq>>>(z, Wm1, N, ntiles_n);
    edge_kernel<<<296, TPB, smem_edge>>>(cent, ei,
                                         We1, be1, We2, be2,
                                         Wm1, bm1,
                                         out, E, N, ntiles_e);
    out_kernel<<<ntiles_n, TPB, smem_out>>>(z, out, Wu1, bu1, Wm2, bm2,
                                            out, N, ntiles_n);
}

// round 15
// speedup vs baseline: 1.1356x; 1.1126x over previous
#include <cuda_runtime.h>

// SPConv fused GNN, R15: 8ch x 8edge thread tile (edges split 4+4 across tile
// halves for conflict-free LDS), PQ added at epilogue, 2 CTAs/SM.

#define TPB 512        // pq/out kernels
#define TPB_E 256      // edge kernel (8 warps)
#define TE 256         // edges (or nodes) per tile
#define AP 260         // activation smem pitch (floats, mult of 4)

typedef unsigned long long ull;

__device__ float g_cnt[65536];
__device__ int g_idx64;
__device__ float g_P[3276800];   // z @ Wm1[0:64]
__device__ float g_Q[3276800];   // z @ Wm1[64:128]

__device__ __forceinline__ void ffma2(ull& acc, ull a, ull b) {
    asm("fma.rn.f32x2 %0, %1, %2, %0;" : "+l"(acc) : "l"(a), "l"(b));
}
__device__ __forceinline__ ull dup2(float w) {
    ull r;
    asm("mov.b64 %0, {%1, %1};" : "=l"(r) : "r"(__float_as_uint(w)));
    return r;
}
__device__ __forceinline__ void unpack2(ull v, float& lo, float& hi) {
    unsigned a, b;
    asm("mov.b64 {%0, %1}, %2;" : "=r"(a), "=r"(b) : "l"(v));
    lo = __uint_as_float(a);
    hi = __uint_as_float(b);
}
__device__ __forceinline__ void red_add_v4(float* p, float x, float y,
                                           float z, float w) {
    asm volatile("red.global.add.v4.f32 [%0], {%1, %2, %3, %4};"
                 :: "l"(p), "f"(x), "f"(y), "f"(z), "f"(w) : "memory");
}

__global__ void detect_kernel(const unsigned long long* __restrict__ ei) {
    if (threadIdx.x == 0 && blockIdx.x == 0) {
        int is64 = 1;
        for (int i = 0; i < 64; ++i)
            if ((ei[i] >> 32) != 0ull) { is64 = 0; break; }
        g_idx64 = is64;
    }
}

__global__ void zero_kernel(float* __restrict__ sums, int total, int n) {
    int i = blockIdx.x * blockDim.x + threadIdx.x;
    if (i < total) sums[i] = 0.0f;
    if (i < n) g_cnt[i] = 0.0f;
}

// ======== edge GEMM: 8 channels x 8 edges (4 + 4 from the two halves) ======
__device__ __forceinline__ void gemm88(const float* __restrict__ H, int hp,
                                       const float* __restrict__ W, int K,
                                       int cb, int eb0, int eb1,
                                       ull acc[4][8]) {
#pragma unroll 4
    for (int k = 0; k < K; ++k) {
        ulonglong2 wA = *reinterpret_cast<const ulonglong2*>(W + k * 64 + cb);
        ulonglong2 wB = *reinterpret_cast<const ulonglong2*>(W + k * 64 + cb + 4);
        ull w2[4] = {wA.x, wA.y, wB.x, wB.y};
        const float* hr = H + k * hp;
        float4 ha = *reinterpret_cast<const float4*>(hr + eb0);
        float4 hb = *reinterpret_cast<const float4*>(hr + eb1);
        ull h2[8] = {dup2(ha.x), dup2(ha.y), dup2(ha.z), dup2(ha.w),
                     dup2(hb.x), dup2(hb.y), dup2(hb.z), dup2(hb.w)};
#pragma unroll
        for (int cp = 0; cp < 4; ++cp)
#pragma unroll
            for (int e = 0; e < 8; ++e)
                ffma2(acc[cp][e], w2[cp], h2[e]);
    }
}

__device__ __forceinline__ void zero88(ull acc[4][8]) {
#pragma unroll
    for (int cp = 0; cp < 4; ++cp)
#pragma unroll
        for (int e = 0; e < 8; ++e) acc[cp][e] = 0ull;
}

// relu(acc + bias) -> D[ch][edges], dense float4 stores at both half-bases
__device__ __forceinline__ void store_relu88(float* __restrict__ D,
                                             ull acc[4][8],
                                             const float* __restrict__ bias,
                                             int cb, int eb0, int eb1) {
#pragma unroll
    for (int cp = 0; cp < 4; ++cp) {
        float lo[8], hi[8];
#pragma unroll
        for (int e = 0; e < 8; ++e) unpack2(acc[cp][e], lo[e], hi[e]);
        float b0 = bias[cb + 2 * cp], b1 = bias[cb + 2 * cp + 1];
        float* r0 = D + (cb + 2 * cp) * AP;
        float* r1 = D + (cb + 2 * cp + 1) * AP;
        *reinterpret_cast<float4*>(r0 + eb0) = make_float4(
            fmaxf(lo[0] + b0, 0.0f), fmaxf(lo[1] + b0, 0.0f),
            fmaxf(lo[2] + b0, 0.0f), fmaxf(lo[3] + b0, 0.0f));
        *reinterpret_cast<float4*>(r0 + eb1) = make_float4(
            fmaxf(lo[4] + b0, 0.0f), fmaxf(lo[5] + b0, 0.0f),
            fmaxf(lo[6] + b0, 0.0f), fmaxf(lo[7] + b0, 0.0f));
        *reinterpret_cast<float4*>(r1 + eb0) = make_float4(
            fmaxf(hi[0] + b1, 0.0f), fmaxf(hi[1] + b1, 0.0f),
            fmaxf(hi[2] + b1, 0.0f), fmaxf(hi[3] + b1, 0.0f));
        *reinterpret_cast<float4*>(r1 + eb1) = make_float4(
            fmaxf(hi[4] + b1, 0.0f), fmaxf(hi[5] + b1, 0.0f),
            fmaxf(hi[6] + b1, 0.0f), fmaxf(hi[7] + b1, 0.0f));
    }
}

// ======== 8ch x 4edge GEMM (pq/out kernels, proven) ========
__device__ __forceinline__ ull pack2(float lo, float hi) {
    ull r;
    asm("mov.b64 %0, {%1, %2};" : "=l"(r)
        : "r"(__float_as_uint(lo)), "r"(__float_as_uint(hi)));
    return r;
}
__device__ __forceinline__ void gemmp(const float* __restrict__ H, int hp,
                                      const float* __restrict__ W, int K,
                                      int cb, int eb, ull acc[4][4]) {
#pragma unroll 4
    for (int k = 0; k < K; ++k) {
        ulonglong2 wA = *reinterpret_cast<const ulonglong2*>(W + k * 64 + cb);
        ulonglong2 wB = *reinterpret_cast<const ulonglong2*>(W + k * 64 + cb + 4);
        ull w2[4] = {wA.x, wA.y, wB.x, wB.y};
        float4 h = *reinterpret_cast<const float4*>(H + k * hp + eb);
        ull h2[4] = {dup2(h.x), dup2(h.y), dup2(h.z), dup2(h.w)};
#pragma unroll
        for (int cp = 0; cp < 4; ++cp)
#pragma unroll
            for (int e = 0; e < 4; ++e)
                ffma2(acc[cp][e], w2[cp], h2[e]);
    }
}

__device__ __forceinline__ void zero_acc(ull acc[4][4]) {
#pragma unroll
    for (int cp = 0; cp < 4; ++cp)
#pragma unroll
        for (int e = 0; e < 4; ++e) acc[cp][e] = 0ull;
}

// ---- pq_kernel: P = z @ Wm1[0:64], Q = z @ Wm1[64:128] ----
// smem: sW 8192 | sZ 64*AP=16640  -> 24832 floats
__global__ __launch_bounds__(TPB) void pq_kernel(
    const float* __restrict__ z, const float* __restrict__ Wm1,
    int N, int ntiles) {
    extern __shared__ float sm[];
    float* sW = sm;
    float* sZ = sm + 8192;
    const int tid = threadIdx.x;
    for (int i = tid; i < 8192; i += TPB) sW[i] = Wm1[i];
    __syncthreads();

    const int wid = tid >> 5, lane = tid & 31;
    const int grp = wid >> 3;
    const int cb = (wid & 7) * 8;
    const int eb = grp * 128 + lane * 4;

    for (int tile = blockIdx.x; tile < ntiles; tile += gridDim.x) {
        const int base = tile * TE;
        for (int i = tid; i < 64 * TE; i += TPB) {
            int nl = i >> 6, k = i & 63;
            int gn = base + nl;
            sZ[k * AP + nl] = (gn < N) ? z[(size_t)gn * 64 + k] : 0.0f;
        }
        __syncthreads();

        ull acc[4][4];
#pragma unroll
        for (int pass = 0; pass < 2; ++pass) {
            zero_acc(acc);
            gemmp(sZ, AP, sW + pass * 64 * 64, 64, cb, eb, acc);
            float* dst = pass == 0 ? g_P : g_Q;
#pragma unroll
            for (int e = 0; e < 4; ++e) {
                int gn = base + eb + e;
                if (gn < N) {
                    float v[8];
#pragma unroll
                    for (int cp = 0; cp < 4; ++cp)
                        unpack2(acc[cp][e], v[2 * cp], v[2 * cp + 1]);
                    *reinterpret_cast<float4*>(&dst[(size_t)gn * 64 + cb]) =
                        make_float4(v[0], v[1], v[2], v[3]);
                    *reinterpret_cast<float4*>(&dst[(size_t)gn * 64 + cb + 4]) =
                        make_float4(v[4], v[5], v[6], v[7]);
                }
            }
        }
        __syncthreads();
    }
}

// ======== edge_kernel (TPB_E=256, 2 CTAs/SM) ========
// smem floats:
//      0 : sWe2  4096
//   4096 : sWm1c 4096  (Wm1 rows 128..191)
//   8192 : sWe1   192
//   8384 : be1 64 | 8448 : be2 64 | 8512 : bm1 64
//   8576 : sDelta 3*AP = 780
//   9356 : sBuf 64*AP = 16640    (e1, then e, reused)
//  25996 : src/dst (2*TE ints = 512 floats)
// total 26508 floats = 106,032 B -> 2 CTAs/SM
__global__ __launch_bounds__(TPB_E, 2) void edge_kernel(
    const float* __restrict__ cent, const void* __restrict__ ei_raw,
    const float* __restrict__ We1, const float* __restrict__ be1,
    const float* __restrict__ We2, const float* __restrict__ be2,
    const float* __restrict__ Wm1, const float* __restrict__ bm1,
    float* __restrict__ S1, int E, int N, int ntiles) {
    extern __shared__ float sm[];
    float* sWe2 = sm;
    float* sWm1c = sm + 4096;
    float* sWe1 = sm + 8192;
    float* sbe1 = sm + 8384;
    float* sbe2 = sm + 8448;
    float* sbm1 = sm + 8512;
    float* sDelta = sm + 8576;
    float* sBuf = sm + 9356;
    int* sSrc = (int*)(sm + 25996);
    int* sDst = sSrc + TE;

    const int tid = threadIdx.x;
    const int idx64 = g_idx64;
    const long long* ei64 = (const long long*)ei_raw;
    const int* ei32 = (const int*)ei_raw;

    for (int i = tid; i < 4096; i += TPB_E) {
        sWe2[i] = We2[i];
        sWm1c[i] = Wm1[128 * 64 + i];
    }
    if (tid < 192) sWe1[tid] = We1[tid];
    if (tid < 64) {
        sbe1[tid] = be1[tid]; sbe2[tid] = be2[tid]; sbm1[tid] = bm1[tid];
    }
    __syncthreads();

    const int wid = tid >> 5, lane = tid & 31;
    const int cb = wid * 8;            // 8 warps x 8 channels = 64
    const int eb0 = lane * 4;          // edges 0..127 (4 per lane)
    const int eb1 = 128 + lane * 4;    // edges 128..255 (4 per lane)

    for (int tile = blockIdx.x; tile < ntiles; tile += gridDim.x) {
        const int base = tile * TE;

        if (tid < TE) {   // TPB_E == TE
            int e = base + tid;
            int s = 0, d = -1;
            if (e < E) {
                if (idx64) { s = (int)ei64[e]; d = (int)ei64[(size_t)E + e]; }
                else       { s = ei32[e];      d = ei32[E + e]; }
                if (s < 0 || s >= N) s = 0;
                if (d < 0 || d >= N) d = 0;
            }
            sSrc[tid] = s;
            sDst[tid] = d;
        }
        __syncthreads();

        // delta = centroids[dst] - centroids[src]
        for (int i = tid; i < 3 * TE; i += TPB_E) {
            int e = i & (TE - 1), comp = i >> 8;
            int s = sSrc[e], d = sDst[e];
            int dd = (d < 0) ? s : d;
            sDelta[comp * AP + e] =
                cent[(size_t)dd * 3 + comp] - cent[(size_t)s * 3 + comp];
        }
        __syncthreads();

        ull acc[4][8];

        // L1: e1 = relu(delta @ We1 + be1) -> sBuf
        zero88(acc);
        gemm88(sDelta, AP, sWe1, 3, cb, eb0, eb1, acc);
        store_relu88(sBuf, acc, sbe1, cb, eb0, eb1);
        __syncthreads();

        // L2: e = relu(e1 @ We2 + be2); reuse sBuf (read -> bar -> write)
        zero88(acc);
        gemm88(sBuf, AP, sWe2, 64, cb, eb0, eb1, acc);
        __syncthreads();                 // all reads of e1 complete
        store_relu88(sBuf, acc, sbe2, cb, eb0, eb1);
        __syncthreads();

        // L3: m1 = relu(e @ Wm1c + P[src] + Q[dst] + bm1) -> scatter S1[dst]
        zero88(acc);
        gemm88(sBuf, AP, sWm1c, 64, cb, eb0, eb1, acc);
#pragma unroll
        for (int e = 0; e < 8; ++e) {
            int ed = (e < 4) ? (eb0 + e) : (eb1 + e - 4);
            int d = sDst[ed];
            if (d >= 0) {
                int s = sSrc[ed];
                float4 p0 = *reinterpret_cast<const float4*>(&g_P[(size_t)s * 64 + cb]);
                float4 p1 = *reinterpret_cast<const float4*>(&g_P[(size_t)s * 64 + cb + 4]);
                float4 q0 = *reinterpret_cast<const float4*>(&g_Q[(size_t)d * 64 + cb]);
                float4 q1 = *reinterpret_cast<const float4*>(&g_Q[(size_t)d * 64 + cb + 4]);
                float v[8];
#pragma unroll
                for (int cp = 0; cp < 4; ++cp)
                    unpack2(acc[cp][e], v[2 * cp], v[2 * cp + 1]);
                v[0] = fmaxf(v[0] + p0.x + q0.x + sbm1[cb + 0], 0.0f);
                v[1] = fmaxf(v[1] + p0.y + q0.y + sbm1[cb + 1], 0.0f);
                v[2] = fmaxf(v[2] + p0.z + q0.z + sbm1[cb + 2], 0.0f);
                v[3] = fmaxf(v[3] + p0.w + q0.w + sbm1[cb + 3], 0.0f);
                v[4] = fmaxf(v[4] + p1.x + q1.x + sbm1[cb + 4], 0.0f);
                v[5] = fmaxf(v[5] + p1.y + q1.y + sbm1[cb + 5], 0.0f);
                v[6] = fmaxf(v[6] + p1.z + q1.z + sbm1[cb + 6], 0.0f);
                v[7] = fmaxf(v[7] + p1.w + q1.w + sbm1[cb + 7], 0.0f);
                float* p = &S1[(size_t)d * 64 + cb];
                red_add_v4(p, v[0], v[1], v[2], v[3]);
                red_add_v4(p + 4, v[4], v[5], v[6], v[7]);
            }
        }
        if (sDst[tid] >= 0) atomicAdd(&g_cnt[sDst[tid]], 1.0f);
        __syncthreads();
    }
}

// ---- out_kernel ----
// M = (S1 @ Wm2 + cnt*bm2) / max(cnt,1);  out = relu([z, M] @ Wu1 + bu1)
// smem floats: 0: sWu1 8192 | 8192: sWm2 4096 | 12288: bu1 64 | 12352: bm2 64
//              12416: sZM 128*AP = 33280   -> 45696 floats
__global__ __launch_bounds__(TPB) void out_kernel(
    const float* __restrict__ z, const float* __restrict__ S1,
    const float* __restrict__ Wu1, const float* __restrict__ bu1,
    const float* __restrict__ Wm2, const float* __restrict__ bm2,
    float* __restrict__ out, int N, int ntiles) {
    extern __shared__ float sm[];
    float* sWu1 = sm;
    float* sWm2 = sm + 8192;
    float* sbu1 = sm + 12288;
    float* sbm2 = sm + 12352;
    float* sZM = sm + 12416;

    const int tid = threadIdx.x;
    for (int i = tid; i < 8192; i += TPB) sWu1[i] = Wu1[i];
    for (int i = tid; i < 4096; i += TPB) sWm2[i] = Wm2[i];
    if (tid < 64) { sbu1[tid] = bu1[tid]; sbm2[tid] = bm2[tid]; }
    __syncthreads();

    const int wid = tid >> 5, lane = tid & 31;
    const int grp = wid >> 3;
    const int cb = (wid & 7) * 8;
    const int eb = grp * 128 + lane * 4;

    for (int tile = blockIdx.x; tile < ntiles; tile += gridDim.x) {
        const int base = tile * TE;
        for (int i = tid; i < 64 * TE; i += TPB) {
            int nl = i >> 6, k = i & 63;
            int gn = base + nl;
            float zv = 0.0f, sv = 0.0f;
            if (gn < N) {
                zv = z[(size_t)gn * 64 + k];
                sv = S1[(size_t)gn * 64 + k];
            }
            sZM[k * AP + nl] = zv;
            sZM[(64 + k) * AP + nl] = sv;
        }
        __syncthreads();

        // stage 1: Mpre = S1tile @ Wm2
        ull acc[4][4];
        zero_acc(acc);
        gemmp(sZM + 64 * AP, AP, sWm2, 64, cb, eb, acc);

        float Mv[4][8];
#pragma unroll
        for (int e = 0; e < 4; ++e) {
            int gn = base + eb + e;
            float c = (gn < N) ? g_cnt[gn] : 0.0f;
            float rinv = 1.0f / fmaxf(c, 1.0f);
#pragma unroll
            for (int cp = 0; cp < 4; ++cp) {
                float lo, hi;
                unpack2(acc[cp][e], lo, hi);
                Mv[e][2 * cp] = (lo + c * sbm2[cb + 2 * cp]) * rinv;
                Mv[e][2 * cp + 1] = (hi + c * sbm2[cb + 2 * cp + 1]) * rinv;
            }
        }
        __syncthreads();

#pragma unroll
        for (int cp = 0; cp < 4; ++cp) {
            float4 v0 = make_float4(Mv[0][2 * cp], Mv[1][2 * cp],
                                    Mv[2][2 * cp], Mv[3][2 * cp]);
            float4 v1 = make_float4(Mv[0][2 * cp + 1], Mv[1][2 * cp + 1],
                                    Mv[2][2 * cp + 1], Mv[3][2 * cp + 1]);
            *reinterpret_cast<float4*>(sZM + (64 + cb + 2 * cp) * AP + eb) = v0;
            *reinterpret_cast<float4*>(sZM + (64 + cb + 2 * cp + 1) * AP + eb) = v1;
        }
        __syncthreads();

        // stage 2: out = relu([z, M] @ Wu1 + bu1)
        zero_acc(acc);
        gemmp(sZM, AP, sWu1, 128, cb, eb, acc);
#pragma unroll
        for (int e = 0; e < 4; ++e) {
            int gn = base + eb + e;
            if (gn < N) {
                float v[8];
#pragma unroll
                for (int cp = 0; cp < 4; ++cp)
                    unpack2(acc[cp][e], v[2 * cp], v[2 * cp + 1]);
                float4 o0, o1;
                o0.x = fmaxf(v[0] + sbu1[cb + 0], 0.0f);
                o0.y = fmaxf(v[1] + sbu1[cb + 1], 0.0f);
                o0.z = fmaxf(v[2] + sbu1[cb + 2], 0.0f);
                o0.w = fmaxf(v[3] + sbu1[cb + 3], 0.0f);
                o1.x = fmaxf(v[4] + sbu1[cb + 4], 0.0f);
                o1.y = fmaxf(v[5] + sbu1[cb + 5], 0.0f);
                o1.z = fmaxf(v[6] + sbu1[cb + 6], 0.0f);
                o1.w = fmaxf(v[7] + sbu1[cb + 7], 0.0f);
                *reinterpret_cast<float4*>(&out[(size_t)gn * 64 + cb]) = o0;
                *reinterpret_cast<float4*>(&out[(size_t)gn * 64 + cb + 4]) = o1;
            }
        }
        __syncthreads();
    }
}

extern "C" void kernel_launch(void* const* d_in, const int* in_sizes, int n_in,
                              void* d_out, int out_size) {
    const float* z    = (const float*)d_in[0];
    const float* cent = (const float*)d_in[1];
    const void* ei    = d_in[2];
    const float* We1 = (const float*)d_in[3];
    const float* be1 = (const float*)d_in[4];
    const float* We2 = (const float*)d_in[5];
    const float* be2 = (const float*)d_in[6];
    const float* Wm1 = (const float*)d_in[7];
    const float* bm1 = (const float*)d_in[8];
    const float* Wm2 = (const float*)d_in[9];
    const float* bm2 = (const float*)d_in[10];
    const float* Wu1 = (const float*)d_in[11];
    const float* bu1 = (const float*)d_in[12];
    float* out = (float*)d_out;

    const int N = in_sizes[0] / 64;
    const int E = in_sizes[2] / 2;
    const int ntiles_e = (E + TE - 1) / TE;
    const int ntiles_n = (N + TE - 1) / TE;

    const size_t smem_edge = 25996 * sizeof(float) + 2 * TE * sizeof(int);
    const size_t smem_pq   = 24832 * sizeof(float);
    const size_t smem_out  = 45696 * sizeof(float);

    cudaFuncSetAttribute(edge_kernel, cudaFuncAttributeMaxDynamicSharedMemorySize,
                         (int)smem_edge);
    cudaFuncSetAttribute(pq_kernel, cudaFuncAttributeMaxDynamicSharedMemorySize,
                         (int)smem_pq);
    cudaFuncSetAttribute(out_kernel, cudaFuncAttributeMaxDynamicSharedMemorySize,
                         (int)smem_out);

    detect_kernel<<<1, 32>>>((const unsigned long long*)ei);
    zero_kernel<<<(N * 64 + 255) / 256, 256>>>(out, N * 64, N);
    pq_kernel<<<ntiles_n, TPB, smem_pq>>>(z, Wm1, N, ntiles_n);
    edge_kernel<<<296, TPB_E, smem_edge>>>(cent, ei,
                                           We1, be1, We2, be2,
                                           Wm1, bm1,
                                           out, E, N, ntiles_e);
    out_kernel<<<ntiles_n, TPB, smem_out>>>(z, out, Wu1, bu1, Wm2, bm2,
                                            out, N, ntiles_n);
}